// round 1
// baseline (speedup 1.0000x reference)
#include <cuda_runtime.h>
#include <cstdint>

#define N_NODES  100000
#define N_EDGES  1200000
#define N_GRAPHS 1024
#define F        64
#define BN_EPS   1e-5f

// ---------------- device scratch (no allocations allowed) ----------------
__device__ float4 g_agg4[N_NODES * (F / 4)];   // 25.6 MB neighbor sums
__device__ float  g_deg[N_NODES];              // in-degree (float)
__device__ int    g_hg[N_GRAPHS * F];          // per-graph max, float bits as int

// ---------------- init: zero scratch every replay ----------------
__global__ void k_init() {
    int i = blockIdx.x * blockDim.x + threadIdx.x;
    int stride = gridDim.x * blockDim.x;
    float* agg = (float*)g_agg4;
    for (int t = i; t < N_NODES * F; t += stride) agg[t] = 0.0f;
    for (int t = i; t < N_NODES;     t += stride) g_deg[t] = 0.0f;
    for (int t = i; t < N_GRAPHS * F; t += stride) g_hg[t] = 0;  // 0 == bits of +0.0f
}

// ---------------- edge aggregation: segment_sum(feats[src], dst) ----------------
// 16 threads per edge, each does one 16B vector RED into agg[dst].
__global__ void k_edges(const float4* __restrict__ feats4,
                        const int* __restrict__ src,
                        const int* __restrict__ dst) {
    long long t = (long long)blockIdx.x * blockDim.x + threadIdx.x;
    if (t >= (long long)N_EDGES * 16) return;
    int e = (int)(t >> 4);
    int q = (int)(t & 15);
    int s = src[e];
    int d = dst[e];
    float4 v = feats4[(long long)s * 16 + q];
    float* p = (float*)&g_agg4[(long long)d * 16 + q];
    asm volatile("red.global.add.v4.f32 [%0], {%1,%2,%3,%4};"
                 :: "l"(p), "f"(v.x), "f"(v.y), "f"(v.z), "f"(v.w)
                 : "memory");
    if (q == 0) atomicAdd(&g_deg[d], 1.0f);
}

// ---------------- node update + relu + per-graph max readout ----------------
// One thread per node; both 64x64 weights in shared; 64 fp32 accumulators.
__global__ void __launch_bounds__(256)
k_node(const float4* __restrict__ feats4,
       const float*  __restrict__ Wself,
       const float*  __restrict__ Wneigh,
       const float*  __restrict__ bneigh,
       const int*    __restrict__ gids) {
    __shared__ float sWs[F * F];
    __shared__ float sWn[F * F];
    for (int i = threadIdx.x; i < F * F; i += 256) {
        sWs[i] = Wself[i];
        sWn[i] = Wneigh[i];
    }
    __syncthreads();

    int node = blockIdx.x * 256 + threadIdx.x;
    if (node >= N_NODES) return;

    float h[F];
#pragma unroll
    for (int o = 0; o < F; o++) h[o] = 0.0f;

    float inv = 1.0f / fmaxf(g_deg[node], 1.0f);

#pragma unroll
    for (int kk = 0; kk < 16; kk++) {
        float4 fs = feats4[(long long)node * 16 + kk];
        float4 fm = g_agg4[(long long)node * 16 + kk];
        float xs[4] = {fs.x, fs.y, fs.z, fs.w};
        float xm[4] = {fm.x * inv, fm.y * inv, fm.z * inv, fm.w * inv};
#pragma unroll
        for (int j = 0; j < 4; j++) {
            int k = kk * 4 + j;
            const float4* wsr = (const float4*)&sWs[k * F];
            const float4* wnr = (const float4*)&sWn[k * F];
#pragma unroll
            for (int o4 = 0; o4 < 16; o4++) {
                float4 ws = wsr[o4];
                float4 wn = wnr[o4];
                h[o4 * 4 + 0] = fmaf(xs[j], ws.x, fmaf(xm[j], wn.x, h[o4 * 4 + 0]));
                h[o4 * 4 + 1] = fmaf(xs[j], ws.y, fmaf(xm[j], wn.y, h[o4 * 4 + 1]));
                h[o4 * 4 + 2] = fmaf(xs[j], ws.z, fmaf(xm[j], wn.z, h[o4 * 4 + 2]));
                h[o4 * 4 + 3] = fmaf(xs[j], ws.w, fmaf(xm[j], wn.w, h[o4 * 4 + 3]));
            }
        }
    }

    int g = gids[node];
#pragma unroll
    for (int o = 0; o < F; o++) {
        float v = fmaxf(h[o] + bneigh[o], 0.0f);   // relu; v >= 0
        atomicMax(&g_hg[g * F + o], __float_as_int(v));  // valid for non-negative floats
    }
}

// ---------------- MLP head with eval-mode BN: one block (128 thr) per graph ----------------
__global__ void __launch_bounds__(128)
k_mlp(const float* __restrict__ W1, const float* __restrict__ b1,
      const float* __restrict__ g1, const float* __restrict__ be1,
      const float* __restrict__ rm1, const float* __restrict__ rv1,
      const float* __restrict__ W2, const float* __restrict__ b2,
      const float* __restrict__ g2, const float* __restrict__ be2,
      const float* __restrict__ rm2, const float* __restrict__ rv2,
      const float* __restrict__ W3, const float* __restrict__ b3,
      float* __restrict__ out) {
    __shared__ float sh[F];
    __shared__ float sx1[128];
    __shared__ float sx2[F];

    int g = blockIdx.x;
    int t = threadIdx.x;

    if (t < F) sh[t] = __int_as_float(g_hg[g * F + t]);
    __syncthreads();

    // layer 1: 64 -> 128, relu, BN
    {
        float a = b1[t];
#pragma unroll 8
        for (int k = 0; k < F; k++) a = fmaf(sh[k], W1[k * 128 + t], a);
        a = fmaxf(a, 0.0f);
        a = (a - rm1[t]) * rsqrtf(rv1[t] + BN_EPS) * g1[t] + be1[t];
        sx1[t] = a;
    }
    __syncthreads();

    // layer 2: 128 -> 64, relu, BN
    if (t < F) {
        float a = b2[t];
#pragma unroll 8
        for (int k = 0; k < 128; k++) a = fmaf(sx1[k], W2[k * F + t], a);
        a = fmaxf(a, 0.0f);
        a = (a - rm2[t]) * rsqrtf(rv2[t] + BN_EPS) * g2[t] + be2[t];
        sx2[t] = a * W3[t];   // fold final matvec weight
    }
    __syncthreads();

    // layer 3: reduce 64 products + b3
    if (t < 32) {
        float r = sx2[t] + sx2[t + 32];
#pragma unroll
        for (int off = 16; off > 0; off >>= 1)
            r += __shfl_down_sync(0xFFFFFFFFu, r, off);
        if (t == 0) out[g] = r + b3[0];
    }
}

// ---------------- launcher ----------------
extern "C" void kernel_launch(void* const* d_in, const int* in_sizes, int n_in,
                              void* d_out, int out_size) {
    const float4* feats4 = (const float4*)d_in[0];
    const int*    src    = (const int*)d_in[1];
    const int*    dst    = (const int*)d_in[2];
    const int*    gids   = (const int*)d_in[3];
    const float*  Wself  = (const float*)d_in[4];
    const float*  Wneigh = (const float*)d_in[5];
    const float*  bneigh = (const float*)d_in[6];
    const float*  W1  = (const float*)d_in[7];
    const float*  b1  = (const float*)d_in[8];
    const float*  g1  = (const float*)d_in[9];
    const float*  be1 = (const float*)d_in[10];
    const float*  rm1 = (const float*)d_in[11];
    const float*  rv1 = (const float*)d_in[12];
    const float*  W2  = (const float*)d_in[13];
    const float*  b2  = (const float*)d_in[14];
    const float*  g2  = (const float*)d_in[15];
    const float*  be2 = (const float*)d_in[16];
    const float*  rm2 = (const float*)d_in[17];
    const float*  rv2 = (const float*)d_in[18];
    const float*  W3  = (const float*)d_in[19];
    const float*  b3  = (const float*)d_in[20];
    float* out = (float*)d_out;

    k_init<<<(N_NODES * F + 255) / 256, 256>>>();

    long long edge_threads = (long long)N_EDGES * 16;
    k_edges<<<(int)((edge_threads + 255) / 256), 256>>>(feats4, src, dst);

    k_node<<<(N_NODES + 255) / 256, 256>>>(feats4, Wself, Wneigh, bneigh, gids);

    k_mlp<<<N_GRAPHS, 128>>>(W1, b1, g1, be1, rm1, rv1,
                             W2, b2, g2, be2, rm2, rv2,
                             W3, b3, out);
}

// round 2
// speedup vs baseline: 1.0859x; 1.0859x over previous
#include <cuda_runtime.h>
#include <cstdint>

#define N_NODES  100000
#define N_EDGES  1200000
#define N_GRAPHS 1024
#define F        64
#define BN_EPS   1e-5f
#define G_PER    16

// ---------------- device scratch (no allocations allowed) ----------------
__device__ float4 g_agg4[N_NODES * (F / 4)];   // 25.6 MB neighbor sums
__device__ float  g_deg[N_NODES];              // in-degree (float)
__device__ int    g_hg[N_GRAPHS * F];          // per-graph max, float bits as int

// ---------------- f32x2 packed helpers ----------------
__device__ __forceinline__ unsigned long long pack2(float x) {
    unsigned long long r;
    asm("mov.b64 %0, {%1, %1};" : "=l"(r) : "f"(x));
    return r;
}
__device__ __forceinline__ void ffma2(unsigned long long& d,
                                      unsigned long long a,
                                      unsigned long long b) {
    asm("fma.rn.f32x2 %0, %1, %2, %0;" : "+l"(d) : "l"(a), "l"(b));
}
__device__ __forceinline__ void unpack2(unsigned long long v, float& lo, float& hi) {
    asm("mov.b64 {%0, %1}, %2;" : "=f"(lo), "=f"(hi) : "l"(v));
}

// ---------------- init: zero scratch every replay (vectorized) ----------------
__global__ void k_init() {
    int i = blockIdx.x * blockDim.x + threadIdx.x;
    int stride = gridDim.x * blockDim.x;
    float4 z = make_float4(0.f, 0.f, 0.f, 0.f);
    for (int t = i; t < N_NODES * (F / 4); t += stride) g_agg4[t] = z;
    float4* deg4 = (float4*)g_deg;
    for (int t = i; t < N_NODES / 4; t += stride) deg4[t] = z;
    int4* hg4 = (int4*)g_hg;
    int4 zi = make_int4(0, 0, 0, 0);
    for (int t = i; t < N_GRAPHS * F / 4; t += stride) hg4[t] = zi;  // 0 == +0.0f bits
}

// ---------------- edge aggregation: segment_sum(feats[src], dst) ----------------
// 16 threads per edge, each does one 16B vector RED into agg[dst].
__global__ void k_edges(const float4* __restrict__ feats4,
                        const int* __restrict__ src,
                        const int* __restrict__ dst) {
    long long t = (long long)blockIdx.x * blockDim.x + threadIdx.x;
    if (t >= (long long)N_EDGES * 16) return;
    int e = (int)(t >> 4);
    int q = (int)(t & 15);
    int s = src[e];
    int d = dst[e];
    float4 v = feats4[(long long)s * 16 + q];
    float* p = (float*)&g_agg4[(long long)d * 16 + q];
    asm volatile("red.global.add.v4.f32 [%0], {%1,%2,%3,%4};"
                 :: "l"(p), "f"(v.x), "f"(v.y), "f"(v.z), "f"(v.w)
                 : "memory");
    if (q == 0) atomicAdd(&g_deg[d], 1.0f);
}

// ---------------- node update + relu + per-graph max readout ----------------
// One thread per node; weights in shared; packed f32x2 accumulators.
__global__ void __launch_bounds__(256)
k_node(const float4* __restrict__ feats4,
       const float*  __restrict__ Wself,
       const float*  __restrict__ Wneigh,
       const float*  __restrict__ bneigh,
       const int*    __restrict__ gids) {
    __shared__ float sWs[F * F];
    __shared__ float sWn[F * F];
    for (int i = threadIdx.x; i < F * F; i += 256) {
        sWs[i] = Wself[i];
        sWn[i] = Wneigh[i];
    }
    __syncthreads();

    int node = blockIdx.x * 256 + threadIdx.x;
    if (node >= N_NODES) return;

    unsigned long long h2[F / 2];
#pragma unroll
    for (int o = 0; o < F / 2; o++) h2[o] = 0ULL;

    float inv = 1.0f / fmaxf(g_deg[node], 1.0f);

#pragma unroll
    for (int kk = 0; kk < 16; kk++) {
        float4 fs = feats4[(long long)node * 16 + kk];
        float4 fm = g_agg4[(long long)node * 16 + kk];
        float xs[4] = {fs.x, fs.y, fs.z, fs.w};
        float xm[4] = {fm.x * inv, fm.y * inv, fm.z * inv, fm.w * inv};
#pragma unroll
        for (int j = 0; j < 4; j++) {
            int k = kk * 4 + j;
            unsigned long long xs2 = pack2(xs[j]);
            unsigned long long xm2 = pack2(xm[j]);
            const ulonglong2* wsr = (const ulonglong2*)&sWs[k * F];
            const ulonglong2* wnr = (const ulonglong2*)&sWn[k * F];
#pragma unroll
            for (int o4 = 0; o4 < 16; o4++) {
                ulonglong2 ws = wsr[o4];   // LDS.128: floats [4o4 .. 4o4+3]
                ulonglong2 wn = wnr[o4];
                ffma2(h2[o4 * 2 + 0], xs2, ws.x);
                ffma2(h2[o4 * 2 + 0], xm2, wn.x);
                ffma2(h2[o4 * 2 + 1], xs2, ws.y);
                ffma2(h2[o4 * 2 + 1], xm2, wn.y);
            }
        }
    }

    int g = gids[node];
#pragma unroll
    for (int o2 = 0; o2 < F / 2; o2++) {
        float lo, hi;
        unpack2(h2[o2], lo, hi);
        float v0 = fmaxf(lo + bneigh[o2 * 2 + 0], 0.0f);   // relu; >= 0
        float v1 = fmaxf(hi + bneigh[o2 * 2 + 1], 0.0f);
        atomicMax(&g_hg[g * F + o2 * 2 + 0], __float_as_int(v0));
        atomicMax(&g_hg[g * F + o2 * 2 + 1], __float_as_int(v1));
    }
}

// ---------------- MLP head: 16 graphs per block, register-cached weights ----------------
__global__ void __launch_bounds__(128)
k_mlp(const float* __restrict__ W1, const float* __restrict__ b1,
      const float* __restrict__ g1, const float* __restrict__ be1,
      const float* __restrict__ rm1, const float* __restrict__ rv1,
      const float* __restrict__ W2, const float* __restrict__ b2,
      const float* __restrict__ g2, const float* __restrict__ be2,
      const float* __restrict__ rm2, const float* __restrict__ rv2,
      const float* __restrict__ W3, const float* __restrict__ b3,
      float* __restrict__ out) {
    __shared__ float sh[G_PER][F];   // inputs for 16 graphs
    __shared__ float sx1[128];       // layer-1 activations (current graph)
    __shared__ float spart[2][F];    // layer-2 partial sums
    __shared__ float sx2[F];         // layer-2 out * W3

    int t = threadIdx.x;
    int g0 = blockIdx.x * G_PER;

    // Cache W1 column t (64 regs) + BN1 params.
    float w1c[F];
#pragma unroll
    for (int k = 0; k < F; k++) w1c[k] = W1[k * 128 + t];
    float bn1_rm = rm1[t];
    float bn1_s  = rsqrtf(rv1[t] + BN_EPS) * g1[t];
    float bn1_be = be1[t];
    float b1t    = b1[t];

    // Cache half a W2 column: thread t handles output j = t&63, k-range half*64..+63.
    int j = t & 63, half = t >> 6;
    float w2c[64];
#pragma unroll
    for (int k = 0; k < 64; k++) w2c[k] = W2[(half * 64 + k) * F + j];
    float bn2_rm = 0.f, bn2_s = 0.f, bn2_be = 0.f, b2t = 0.f, w3t = 0.f;
    if (t < F) {
        bn2_rm = rm2[t];
        bn2_s  = rsqrtf(rv2[t] + BN_EPS) * g2[t];
        bn2_be = be2[t];
        b2t    = b2[t];
        w3t    = W3[t];
    }
    float b3v = b3[0];

    // Load the 16 graph vectors.
    for (int i = t; i < G_PER * F; i += 128)
        sh[i / F][i % F] = __int_as_float(g_hg[(g0 + i / F) * F + (i % F)]);
    __syncthreads();

    for (int gg = 0; gg < G_PER; gg++) {
        // layer 1: 64 -> 128, relu, BN (4 split accumulators)
        float a0 = 0.f, a1 = 0.f, a2 = 0.f, a3 = 0.f;
#pragma unroll
        for (int k = 0; k < F; k += 4) {
            a0 = fmaf(sh[gg][k + 0], w1c[k + 0], a0);
            a1 = fmaf(sh[gg][k + 1], w1c[k + 1], a1);
            a2 = fmaf(sh[gg][k + 2], w1c[k + 2], a2);
            a3 = fmaf(sh[gg][k + 3], w1c[k + 3], a3);
        }
        float a = (a0 + a1) + (a2 + a3) + b1t;
        a = fmaxf(a, 0.0f);
        sx1[t] = (a - bn1_rm) * bn1_s + bn1_be;
        __syncthreads();

        // layer 2 partials: each thread sums 64 of the 128 k's for output j
        float c0 = 0.f, c1 = 0.f, c2 = 0.f, c3 = 0.f;
        const float* x1h = &sx1[half * 64];
#pragma unroll
        for (int k = 0; k < 64; k += 4) {
            c0 = fmaf(x1h[k + 0], w2c[k + 0], c0);
            c1 = fmaf(x1h[k + 1], w2c[k + 1], c1);
            c2 = fmaf(x1h[k + 2], w2c[k + 2], c2);
            c3 = fmaf(x1h[k + 3], w2c[k + 3], c3);
        }
        spart[half][j] = (c0 + c1) + (c2 + c3);
        __syncthreads();

        if (t < F) {
            float x = spart[0][t] + spart[1][t] + b2t;
            x = fmaxf(x, 0.0f);
            x = (x - bn2_rm) * bn2_s + bn2_be;
            sx2[t] = x * w3t;   // fold final matvec weight
        }
        __syncthreads();

        if (t < 32) {
            float r = sx2[t] + sx2[t + 32];
#pragma unroll
            for (int off = 16; off > 0; off >>= 1)
                r += __shfl_down_sync(0xFFFFFFFFu, r, off);
            if (t == 0) out[g0 + gg] = r + b3v;
        }
        __syncthreads();   // protect sx1/sx2 before next graph
    }
}

// ---------------- launcher ----------------
extern "C" void kernel_launch(void* const* d_in, const int* in_sizes, int n_in,
                              void* d_out, int out_size) {
    const float4* feats4 = (const float4*)d_in[0];
    const int*    src    = (const int*)d_in[1];
    const int*    dst    = (const int*)d_in[2];
    const int*    gids   = (const int*)d_in[3];
    const float*  Wself  = (const float*)d_in[4];
    const float*  Wneigh = (const float*)d_in[5];
    const float*  bneigh = (const float*)d_in[6];
    const float*  W1  = (const float*)d_in[7];
    const float*  b1  = (const float*)d_in[8];
    const float*  g1  = (const float*)d_in[9];
    const float*  be1 = (const float*)d_in[10];
    const float*  rm1 = (const float*)d_in[11];
    const float*  rv1 = (const float*)d_in[12];
    const float*  W2  = (const float*)d_in[13];
    const float*  b2  = (const float*)d_in[14];
    const float*  g2  = (const float*)d_in[15];
    const float*  be2 = (const float*)d_in[16];
    const float*  rm2 = (const float*)d_in[17];
    const float*  rv2 = (const float*)d_in[18];
    const float*  W3  = (const float*)d_in[19];
    const float*  b3  = (const float*)d_in[20];
    float* out = (float*)d_out;

    k_init<<<1600, 256>>>();

    long long edge_threads = (long long)N_EDGES * 16;
    k_edges<<<(int)((edge_threads + 255) / 256), 256>>>(feats4, src, dst);

    k_node<<<(N_NODES + 255) / 256, 256>>>(feats4, Wself, Wneigh, bneigh, gids);

    k_mlp<<<N_GRAPHS / G_PER, 128>>>(W1, b1, g1, be1, rm1, rv1,
                                     W2, b2, g2, be2, rm2, rv2,
                                     W3, b3, out);
}

// round 5
// speedup vs baseline: 1.1212x; 1.0325x over previous
#include <cuda_runtime.h>
#include <cstdint>

#define N_NODES  100000
#define N_EDGES  1200000
#define N_GRAPHS 1024
#define F        64
#define BN_EPS   1e-5f
#define SCAN_BLOCKS 98          // ceil(100000/1024)

// ---------------- device scratch (no allocations allowed) ----------------
__device__ float4 g_agg4[N_NODES * (F / 4)];   // 25.6 MB neighbor MEANS (fully overwritten)
__device__ int    g_cnt[N_NODES];              // in-degree
__device__ int    g_off[N_NODES];              // CSR offsets (exclusive scan of cnt)
__device__ int    g_cursor[N_NODES];           // scatter cursors
__device__ int    g_esrc[N_EDGES];             // src ids grouped by dst
__device__ int    g_blocksum[128];             // scan partials
__device__ int    g_hg[N_GRAPHS * F];          // per-graph max, float bits as int

// ---------------- f32x2 packed helpers ----------------
__device__ __forceinline__ unsigned long long pack2(float x) {
    unsigned long long r;
    asm("mov.b64 %0, {%1, %1};" : "=l"(r) : "f"(x));
    return r;
}
__device__ __forceinline__ void ffma2(unsigned long long& d,
                                      unsigned long long a,
                                      unsigned long long b) {
    asm("fma.rn.f32x2 %0, %1, %2, %0;" : "+l"(d) : "l"(a), "l"(b));
}
__device__ __forceinline__ void unpack2(unsigned long long v, float& lo, float& hi) {
    asm("mov.b64 {%0, %1}, %2;" : "=f"(lo), "=f"(hi) : "l"(v));
}

// ---------------- init: zero counters + readout only (664KB) ----------------
__global__ void k_init() {
    int i = blockIdx.x * blockDim.x + threadIdx.x;
    int stride = gridDim.x * blockDim.x;
    int4 zi = make_int4(0, 0, 0, 0);
    int4* cnt4 = (int4*)g_cnt;
    for (int t = i; t < N_NODES / 4; t += stride) cnt4[t] = zi;
    g_cnt[N_NODES - 1] = 0; g_cnt[N_NODES - 2] = 0; g_cnt[N_NODES - 3] = 0; // tail (100000%4==0 anyway, keep safe)
    int4* hg4 = (int4*)g_hg;
    for (int t = i; t < N_GRAPHS * F / 4; t += stride) hg4[t] = zi;  // 0 == +0.0f bits
}

// ---------------- degree histogram ----------------
__global__ void k_hist(const int* __restrict__ dst) {
    int e = blockIdx.x * blockDim.x + threadIdx.x;
    if (e < N_EDGES) atomicAdd(&g_cnt[dst[e]], 1);
}

// ---------------- scan stage 1: per-block exclusive scan (Hillis-Steele) ----------------
__global__ void __launch_bounds__(1024) k_scan1() {
    __shared__ int s[1024];
    int tid = threadIdx.x;
    int i = blockIdx.x * 1024 + tid;
    int v = (i < N_NODES) ? g_cnt[i] : 0;
    s[tid] = v;
    __syncthreads();
#pragma unroll
    for (int d = 1; d < 1024; d <<= 1) {
        int t = (tid >= d) ? s[tid - d] : 0;
        __syncthreads();
        s[tid] += t;
        __syncthreads();
    }
    if (i < N_NODES) g_off[i] = s[tid] - v;        // exclusive within block
    if (tid == 1023) g_blocksum[blockIdx.x] = s[1023];
}

// ---------------- scan stage 2: scan the 98 block totals ----------------
__global__ void k_scan2() {
    __shared__ int s[128];
    int t = threadIdx.x;
    s[t] = (t < SCAN_BLOCKS) ? g_blocksum[t] : 0;
    __syncthreads();
    if (t == 0) {
        int acc = 0;
        for (int b = 0; b < SCAN_BLOCKS; b++) { int v = s[b]; s[b] = acc; acc += v; }
    }
    __syncthreads();
    if (t < SCAN_BLOCKS) g_blocksum[t] = s[t];
}

// ---------------- scan stage 3: add block offsets, seed cursors ----------------
__global__ void __launch_bounds__(1024) k_scan3() {
    int i = blockIdx.x * 1024 + threadIdx.x;
    if (i < N_NODES) {
        int v = g_off[i] + g_blocksum[blockIdx.x];
        g_off[i] = v;
        g_cursor[i] = v;
    }
}

// ---------------- scatter: bucket src ids by dst ----------------
__global__ void k_scatter(const int* __restrict__ src, const int* __restrict__ dst) {
    int e = blockIdx.x * blockDim.x + threadIdx.x;
    if (e < N_EDGES) {
        int p = atomicAdd(&g_cursor[dst[e]], 1);
        g_esrc[p] = src[e];
    }
}

// ---------------- gather-aggregate: mean of neighbor feats, no atomics ----------------
// 16 threads per node; thread q owns float4 column q. Coalesced 256B row reads.
__global__ void __launch_bounds__(256) k_gather(const float4* __restrict__ feats4) {
    int t = blockIdx.x * 256 + threadIdx.x;
    int node = t >> 4;
    int q = t & 15;
    if (node >= N_NODES) return;
    int start = g_off[node];
    int n = g_cnt[node];
    float4 acc = make_float4(0.f, 0.f, 0.f, 0.f);
    const int* ep = &g_esrc[start];
    for (int i = 0; i < n; i++) {
        int s = ep[i];                       // same addr across the 16-group: L1 broadcast
        float4 v = feats4[(long long)s * 16 + q];
        acc.x += v.x; acc.y += v.y; acc.z += v.z; acc.w += v.w;
    }
    float inv = 1.0f / (float)max(n, 1);
    acc.x *= inv; acc.y *= inv; acc.z *= inv; acc.w *= inv;
    g_agg4[(long long)node * 16 + q] = acc;  // stores the MEAN
}

// ---------------- node update + relu + per-graph max readout ----------------
__global__ void __launch_bounds__(256)
k_node(const float4* __restrict__ feats4,
       const float*  __restrict__ Wself,
       const float*  __restrict__ Wneigh,
       const float*  __restrict__ bneigh,
       const int*    __restrict__ gids) {
    __shared__ float sWs[F * F];
    __shared__ float sWn[F * F];
    for (int i = threadIdx.x; i < F * F; i += 256) {
        sWs[i] = Wself[i];
        sWn[i] = Wneigh[i];
    }
    __syncthreads();

    int node = blockIdx.x * 256 + threadIdx.x;
    if (node >= N_NODES) return;

    unsigned long long h2[F / 2];
#pragma unroll
    for (int o = 0; o < F / 2; o++) h2[o] = 0ULL;

#pragma unroll
    for (int kk = 0; kk < 16; kk++) {
        float4 fs = feats4[(long long)node * 16 + kk];
        float4 fm = g_agg4[(long long)node * 16 + kk];   // already the mean
        float xs[4] = {fs.x, fs.y, fs.z, fs.w};
        float xm[4] = {fm.x, fm.y, fm.z, fm.w};
#pragma unroll
        for (int j = 0; j < 4; j++) {
            int k = kk * 4 + j;
            unsigned long long xs2 = pack2(xs[j]);
            unsigned long long xm2 = pack2(xm[j]);
            const ulonglong2* wsr = (const ulonglong2*)&sWs[k * F];
            const ulonglong2* wnr = (const ulonglong2*)&sWn[k * F];
#pragma unroll
            for (int o4 = 0; o4 < 16; o4++) {
                ulonglong2 ws = wsr[o4];   // LDS.128, warp-broadcast
                ulonglong2 wn = wnr[o4];
                ffma2(h2[o4 * 2 + 0], xs2, ws.x);
                ffma2(h2[o4 * 2 + 0], xm2, wn.x);
                ffma2(h2[o4 * 2 + 1], xs2, ws.y);
                ffma2(h2[o4 * 2 + 1], xm2, wn.y);
            }
        }
    }

    int g = gids[node];
#pragma unroll
    for (int o2 = 0; o2 < F / 2; o2++) {
        float lo, hi;
        unpack2(h2[o2], lo, hi);
        float v0 = fmaxf(lo + bneigh[o2 * 2 + 0], 0.0f);   // relu; >= 0
        float v1 = fmaxf(hi + bneigh[o2 * 2 + 1], 0.0f);
        atomicMax(&g_hg[g * F + o2 * 2 + 0], __float_as_int(v0));
        atomicMax(&g_hg[g * F + o2 * 2 + 1], __float_as_int(v1));
    }
}

// ---------------- MLP head: one warp per graph, no block syncs ----------------
__global__ void __launch_bounds__(128)
k_mlp(const float* __restrict__ W1, const float* __restrict__ b1,
      const float* __restrict__ g1, const float* __restrict__ be1,
      const float* __restrict__ rm1, const float* __restrict__ rv1,
      const float* __restrict__ W2, const float* __restrict__ b2,
      const float* __restrict__ g2, const float* __restrict__ be2,
      const float* __restrict__ rm2, const float* __restrict__ rv2,
      const float* __restrict__ W3, const float* __restrict__ b3,
      float* __restrict__ out) {
    __shared__ float sh[4][F];     // per-warp layer-0 input
    __shared__ float sy[4][128];   // per-warp layer-1 output

    int w = threadIdx.x >> 5;
    int lane = threadIdx.x & 31;
    int g = blockIdx.x * 4 + w;

    sh[w][lane]      = __int_as_float(g_hg[g * F + lane]);
    sh[w][lane + 32] = __int_as_float(g_hg[g * F + lane + 32]);
    __syncwarp();

    // layer 1: 64 -> 128; lane computes outputs j = lane + 32*m
    float a0 = b1[lane], a1 = b1[lane + 32], a2 = b1[lane + 64], a3 = b1[lane + 96];
#pragma unroll 8
    for (int k = 0; k < F; k++) {
        float xv = sh[w][k];                    // LDS broadcast
        const float* wr = &W1[k * 128 + lane];  // coalesced 512B per k
        a0 = fmaf(xv, wr[0],  a0);
        a1 = fmaf(xv, wr[32], a1);
        a2 = fmaf(xv, wr[64], a2);
        a3 = fmaf(xv, wr[96], a3);
    }
    {
        float acc[4] = {a0, a1, a2, a3};
#pragma unroll
        for (int m = 0; m < 4; m++) {
            int j = lane + 32 * m;
            float a = fmaxf(acc[m], 0.0f);
            a = (a - rm1[j]) * rsqrtf(rv1[j] + BN_EPS) * g1[j] + be1[j];
            sy[w][j] = a;
        }
    }
    __syncwarp();

    // layer 2: 128 -> 64; lane computes outputs j = lane, lane+32
    float c0 = b2[lane], c1 = b2[lane + 32];
#pragma unroll 8
    for (int k = 0; k < 128; k++) {
        float yv = sy[w][k];                    // LDS broadcast
        const float* wr = &W2[k * F + lane];    // coalesced 256B per k
        c0 = fmaf(yv, wr[0],  c0);
        c1 = fmaf(yv, wr[32], c1);
    }
    float p;
    {
        int j0 = lane, j1 = lane + 32;
        float x0 = fmaxf(c0, 0.0f);
        x0 = (x0 - rm2[j0]) * rsqrtf(rv2[j0] + BN_EPS) * g2[j0] + be2[j0];
        float x1 = fmaxf(c1, 0.0f);
        x1 = (x1 - rm2[j1]) * rsqrtf(rv2[j1] + BN_EPS) * g2[j1] + be2[j1];
        p = x0 * W3[j0] + x1 * W3[j1];
    }
#pragma unroll
    for (int off = 16; off > 0; off >>= 1)
        p += __shfl_down_sync(0xFFFFFFFFu, p, off);
    if (lane == 0) out[g] = p + b3[0];
}

// ---------------- launcher ----------------
extern "C" void kernel_launch(void* const* d_in, const int* in_sizes, int n_in,
                              void* d_out, int out_size) {
    const float4* feats4 = (const float4*)d_in[0];
    const int*    src    = (const int*)d_in[1];
    const int*    dst    = (const int*)d_in[2];
    const int*    gids   = (const int*)d_in[3];
    const float*  Wself  = (const float*)d_in[4];
    const float*  Wneigh = (const float*)d_in[5];
    const float*  bneigh = (const float*)d_in[6];
    const float*  W1  = (const float*)d_in[7];
    const float*  b1  = (const float*)d_in[8];
    const float*  g1  = (const float*)d_in[9];
    const float*  be1 = (const float*)d_in[10];
    const float*  rm1 = (const float*)d_in[11];
    const float*  rv1 = (const float*)d_in[12];
    const float*  W2  = (const float*)d_in[13];
    const float*  b2  = (const float*)d_in[14];
    const float*  g2  = (const float*)d_in[15];
    const float*  be2 = (const float*)d_in[16];
    const float*  rm2 = (const float*)d_in[17];
    const float*  rv2 = (const float*)d_in[18];
    const float*  W3  = (const float*)d_in[19];
    const float*  b3  = (const float*)d_in[20];
    float* out = (float*)d_out;

    k_init<<<296, 256>>>();
    k_hist<<<(N_EDGES + 255) / 256, 256>>>(dst);
    k_scan1<<<SCAN_BLOCKS, 1024>>>();
    k_scan2<<<1, 128>>>();
    k_scan3<<<SCAN_BLOCKS, 1024>>>();
    k_scatter<<<(N_EDGES + 255) / 256, 256>>>(src, dst);
    k_gather<<<(N_NODES * 16 + 255) / 256, 256>>>(feats4);
    k_node<<<(N_NODES + 255) / 256, 256>>>(feats4, Wself, Wneigh, bneigh, gids);
    k_mlp<<<N_GRAPHS / 4, 128>>>(W1, b1, g1, be1, rm1, rv1,
                                 W2, b2, g2, be2, rm2, rv2,
                                 W3, b3, out);
}